// round 4
// baseline (speedup 1.0000x reference)
#include <cuda_runtime.h>
#include <cuda_bf16.h>

// NV12 -> RGB, 4K frame. 4 pixels per thread.
// d_in[0]: int32 flattened: [0 : 7680*4320) full-res Y, then (2160,3840,2) UV.
// d_in[1]: float32[9] yuv_to_rgb (row-major 3x3), d_in[2]: float32[3] offset.
// out: float32 (2160, 3840, 3): rgb[j] = sum_i (yuv[i]-off[i]) * M[i][j],
// yuv = [Y[2r,2c], U[r,c], V[r,c]].

#define HH 2160
#define HW 3840
#define FULL_W (HW * 2)            // 7680
#define Y_ELEMS (FULL_W * HH * 2)  // 33177600
#define QPR (HW / 4)               // 960 quads per row
#define NQUADS (HH * QPR)          // 2073600 = 8100 * 256 exactly

__global__ __launch_bounds__(256)
void nv12_to_rgb_kernel(const int* __restrict__ data,
                        const float* __restrict__ M,
                        const float* __restrict__ off,
                        float* __restrict__ out)
{
    int idx = blockIdx.x * blockDim.x + threadIdx.x;  // quad index
    if (idx >= NQUADS) return;

    int r = idx / QPR;
    int c = (idx - r * QPR) * 4;  // half-res col, multiple of 4

    // Front-batched loads: MLP_p1 = 4.
    // Y: full-res row 2r, cols 2c..2c+7 -> two int4 (use .x/.z of each).
    const int4* yp = reinterpret_cast<const int4*>(data + (2 * r) * FULL_W + 2 * c);
    const int4 ya = yp[0];
    const int4 yb = yp[1];
    // UV: 8 consecutive ints = (u,v) x 4 pixels -> two int4.
    const int4* uvp = reinterpret_cast<const int4*>(data + Y_ELEMS + (r * HW + c) * 2);
    const int4 uva = uvp[0];
    const int4 uvb = uvp[1];

    // Matrix + offset: uniform addresses -> L1 broadcast.
    const float m00 = __ldg(M + 0), m01 = __ldg(M + 1), m02 = __ldg(M + 2);
    const float m10 = __ldg(M + 3), m11 = __ldg(M + 4), m12 = __ldg(M + 5);
    const float m20 = __ldg(M + 6), m21 = __ldg(M + 7), m22 = __ldg(M + 8);
    const float o0 = __ldg(off + 0), o1 = __ldg(off + 1), o2 = __ldg(off + 2);

    float yy[4] = { (float)ya.x - o0, (float)ya.z - o0,
                    (float)yb.x - o0, (float)yb.z - o0 };
    float uu[4] = { (float)uva.x - o1, (float)uva.z - o1,
                    (float)uvb.x - o1, (float)uvb.z - o1 };
    float vv[4] = { (float)uva.y - o2, (float)uva.w - o2,
                    (float)uvb.y - o2, (float)uvb.w - o2 };

    float rgb[12];
#pragma unroll
    for (int p = 0; p < 4; p++) {
        rgb[p * 3 + 0] = yy[p] * m00 + uu[p] * m10 + vv[p] * m20;
        rgb[p * 3 + 1] = yy[p] * m01 + uu[p] * m11 + vv[p] * m21;
        rgb[p * 3 + 2] = yy[p] * m02 + uu[p] * m12 + vv[p] * m22;
    }

    // 12 consecutive floats, 16B-aligned base -> 3x STG.128.
    float4* o = reinterpret_cast<float4*>(out + (r * HW + c) * 3);
    o[0] = make_float4(rgb[0], rgb[1], rgb[2], rgb[3]);
    o[1] = make_float4(rgb[4], rgb[5], rgb[6], rgb[7]);
    o[2] = make_float4(rgb[8], rgb[9], rgb[10], rgb[11]);
}

extern "C" void kernel_launch(void* const* d_in, const int* in_sizes, int n_in,
                              void* d_out, int out_size)
{
    const int*   data = (const int*)d_in[0];
    const float* M    = (const float*)d_in[1];
    const float* off  = (const float*)d_in[2];
    float*       out  = (float*)d_out;

    const int threads = 256;
    const int blocks  = NQUADS / threads;  // 8100 exactly
    nv12_to_rgb_kernel<<<blocks, threads>>>(data, M, off, out);
}

// round 5
// speedup vs baseline: 1.0065x; 1.0065x over previous
#include <cuda_runtime.h>
#include <cuda_bf16.h>

// NV12 -> RGB, 4K frame. 2 pixels/thread x 2 far-apart regions (MLP=4,
// per-warp-contiguous loads).
// d_in[0]: int32 flattened: [0 : 7680*4320) full-res Y, then (2160,3840,2) UV.
// d_in[1]: float32[9] yuv_to_rgb (row-major 3x3), d_in[2]: float32[3] offset.
// out: float32 (2160, 3840, 3): rgb[j] = sum_i (yuv[i]-off[i]) * M[i][j],
// yuv = [Y[2r,2c], U[r,c], V[r,c]].

#define HH 2160
#define HW 3840
#define FULL_W (HW * 2)            // 7680
#define Y_ELEMS (FULL_W * HH * 2)  // 33177600
#define PPR (HW / 2)               // 1920 pairs per row
#define NPAIRS (HH * PPR)          // 4147200
#define HALFP (NPAIRS / 2)         // 2073600 = 8100 * 256 exactly

__global__ __launch_bounds__(256)
void nv12_to_rgb_kernel(const int* __restrict__ data,
                        const float* __restrict__ M,
                        const float* __restrict__ off,
                        float* __restrict__ out)
{
    int idx = blockIdx.x * blockDim.x + threadIdx.x;  // pair index, region 0
    if (idx >= HALFP) return;

    // Region 0: rows [0, 1080). Region 1: rows [1080, 2160).
    int r0 = idx / PPR;
    int c0 = (idx - r0 * PPR) * 2;          // even half-res col
    int r1 = r0 + HH / 2;
    int c1 = c0;

    // Front-batch 4 independent, warp-contiguous LDG.128s (16B thread stride).
    const int4 yv0 = __ldcs(reinterpret_cast<const int4*>(
        data + (2 * r0) * FULL_W + 2 * c0));
    const int4 yv1 = __ldcs(reinterpret_cast<const int4*>(
        data + (2 * r1) * FULL_W + 2 * c1));
    const int4 uv0 = __ldcs(reinterpret_cast<const int4*>(
        data + Y_ELEMS + (r0 * HW + c0) * 2));
    const int4 uv1 = __ldcs(reinterpret_cast<const int4*>(
        data + Y_ELEMS + (r1 * HW + c1) * 2));

    // Matrix + offset: uniform addresses -> L1 broadcast.
    const float m00 = __ldg(M + 0), m01 = __ldg(M + 1), m02 = __ldg(M + 2);
    const float m10 = __ldg(M + 3), m11 = __ldg(M + 4), m12 = __ldg(M + 5);
    const float m20 = __ldg(M + 6), m21 = __ldg(M + 7), m22 = __ldg(M + 8);
    const float o0 = __ldg(off + 0), o1 = __ldg(off + 1), o2 = __ldg(off + 2);

    // ---- region 0 ----
    {
        float ya = (float)yv0.x - o0, yb = (float)yv0.z - o0;
        float ua = (float)uv0.x - o1, ub = (float)uv0.z - o1;
        float va = (float)uv0.y - o2, vb = (float)uv0.w - o2;

        float ra = ya * m00 + ua * m10 + va * m20;
        float ga = ya * m01 + ua * m11 + va * m21;
        float ba = ya * m02 + ua * m12 + va * m22;
        float rb = yb * m00 + ub * m10 + vb * m20;
        float gb = yb * m01 + ub * m11 + vb * m21;
        float bb = yb * m02 + ub * m12 + vb * m22;

        float* o = out + (r0 * HW + c0) * 3;  // 8B-aligned (c0 even)
        reinterpret_cast<float2*>(o)[0] = make_float2(ra, ga);
        reinterpret_cast<float2*>(o)[1] = make_float2(ba, rb);
        reinterpret_cast<float2*>(o)[2] = make_float2(gb, bb);
    }

    // ---- region 1 ----
    {
        float ya = (float)yv1.x - o0, yb = (float)yv1.z - o0;
        float ua = (float)uv1.x - o1, ub = (float)uv1.z - o1;
        float va = (float)uv1.y - o2, vb = (float)uv1.w - o2;

        float ra = ya * m00 + ua * m10 + va * m20;
        float ga = ya * m01 + ua * m11 + va * m21;
        float ba = ya * m02 + ua * m12 + va * m22;
        float rb = yb * m00 + ub * m10 + vb * m20;
        float gb = yb * m01 + ub * m11 + vb * m21;
        float bb = yb * m02 + ub * m12 + vb * m22;

        float* o = out + (r1 * HW + c1) * 3;
        reinterpret_cast<float2*>(o)[0] = make_float2(ra, ga);
        reinterpret_cast<float2*>(o)[1] = make_float2(ba, rb);
        reinterpret_cast<float2*>(o)[2] = make_float2(gb, bb);
    }
}

extern "C" void kernel_launch(void* const* d_in, const int* in_sizes, int n_in,
                              void* d_out, int out_size)
{
    const int*   data = (const int*)d_in[0];
    const float* M    = (const float*)d_in[1];
    const float* off  = (const float*)d_in[2];
    float*       out  = (float*)d_out;

    const int threads = 256;
    const int blocks  = HALFP / threads;  // 8100 exactly
    nv12_to_rgb_kernel<<<blocks, threads>>>(data, M, off, out);
}